// round 15
// baseline (speedup 1.0000x reference)
#include <cuda_runtime.h>

// LePEAttention: out = Q (K^T V) * 2/sqrt(32); no softmax. 128 batches (t,b,win,head),
// each: Q,K,V = [32 ch][1568 pos], pos = 56 rows x 28 cols (win selects col half).

#define HW4    784                 // 3136/4
#define NB     128
#define SROW   29                  // k/v row stride in float4 units (28 + 1 pad)
#define CH_F4  (32 * SROW)
#define BUF_F4 (2 * CH_F4)         // K + V one chunk (<=4 strided rows)
#define P1_SMEM (2 * BUF_F4 * 16)  // 59392 B double buffered -> 3 CTAs/SM
#define P2_SMEM 32768              // sQ[1792] f4 + sM[1024] f32
#define SCALE2 0.35355339059327373f

__device__ float g_part[NB * 4 * 1024];   // 4 rowmod-partials per batch

#define FFMA2(d, a, b) \
    asm("fma.rn.f32x2 %0, %1, %2, %0;" : "+l"(d) : "l"(a), "l"(b))

__device__ __forceinline__ unsigned long long pack2(float x, float y) {
    unsigned long long r;
    asm("mov.b64 %0, {%1,%2};" : "=l"(r) : "f"(x), "f"(y));
    return r;
}
__device__ __forceinline__ float2 unpack2(unsigned long long a) {
    float2 f;
    asm("mov.b64 {%0,%1}, %2;" : "=f"(f.x), "=f"(f.y) : "l"(a));
    return f;
}
__device__ __forceinline__ void cp16(void* dst, const void* src) {
    unsigned d = (unsigned)__cvta_generic_to_shared(dst);
    asm volatile("cp.async.cg.shared.global [%0], [%1], 16;" :: "r"(d), "l"(src));
}

// ===== Pass 1: M partial over rows {rm, rm+4, ..., rm+52}; 512 CTAs, 3/SM =====
// chunk c covers strided-row indices k in [KB[c], KB[c]+NK[c]):
//   KB = {0,4,8,11}, NK = {4,4,3,3}  (14 strided rows total)
__global__ __launch_bounds__(224, 3) void p1(const float* __restrict__ K,
                                             const float* __restrict__ V) {
    extern __shared__ float4 smem[];

    const int tid   = threadIdx.x;
    const int rm    = blockIdx.x;       // row mod 4
    const int batch = blockIdx.y;
    const int h   = batch & 7;
    const int win = (batch >> 3) & 1;
    const int tb  = batch >> 4;
    const int base4 = (tb * 256 + h * 32) * HW4 + win * 7;

    const float4* Kp = (const float4*)K;
    const float4* Vp = (const float4*)V;

    // affine slot geometry: slot t covers ch = ch0 + 8t (224 = 8*28)
    const int ch0     = tid / 28;
    const int u0      = tid - ch0 * 28;       // 0..27 = k_local*7 + cu
    const int k_local = u0 / 7;               // 0..3
    const int smK     = ch0 * SROW + u0;      // f4 units
    const int gK      = base4 + ch0 * HW4 + (rm + 4 * k_local) * 14 + (u0 - k_local * 7);

    const int lane = tid & 31;
    const int warp = tid >> 5;          // 7 warps
    const int d1g  = lane & 3;          // k-ch {d1g + 4i}
    const int d2g  = lane >> 2;         // v-ch {d2g + 8j}: stride 29 odd -> CF

    unsigned long long acc[8][4];
    #pragma unroll
    for (int i = 0; i < 8; i++)
        #pragma unroll
        for (int j = 0; j < 4; j++) acc[i][j] = 0ull;

    // load chunk c into buffer buf (predicated on k_local < NK[c])
    #define P1_LOAD(c_, nk_, kb_, buf_)                                         \
        if (k_local < (nk_)) {                                                  \
            _Pragma("unroll")                                                   \
            for (int t = 0; t < 4; ++t) {                                       \
                cp16(&smem[(buf_) * BUF_F4 + smK + t * 8 * SROW],               \
                     Kp + gK + (kb_) * 56 + t * 8 * HW4);                       \
                cp16(&smem[(buf_) * BUF_F4 + CH_F4 + smK + t * 8 * SROW],       \
                     Vp + gK + (kb_) * 56 + t * 8 * HW4);                       \
            }                                                                   \
        }                                                                       \
        asm volatile("cp.async.commit_group;");

    #define P1_COMPUTE(nk_, buf_)                                               \
        {                                                                       \
            const float4* sK = &smem[(buf_) * BUF_F4];                          \
            const float4* sV = sK + CH_F4;                                      \
            _Pragma("unroll")                                                   \
            for (int qq = 0; qq < (nk_); ++qq) {                                \
                const int p4 = (nk_) * warp + qq;                               \
                ulonglong2 vf[4];                                               \
                _Pragma("unroll")                                               \
                for (int j = 0; j < 4; j++)                                     \
                    vf[j] = *reinterpret_cast<const ulonglong2*>(               \
                        &sV[(d2g + 8 * j) * SROW + p4]);                        \
                _Pragma("unroll")                                               \
                for (int i = 0; i < 8; i++) {                                   \
                    ulonglong2 kf = *reinterpret_cast<const ulonglong2*>(       \
                        &sK[(d1g + 4 * i) * SROW + p4]);                        \
                    _Pragma("unroll")                                           \
                    for (int j = 0; j < 4; j++) {                               \
                        FFMA2(acc[i][j], kf.x, vf[j].x);                        \
                        FFMA2(acc[i][j], kf.y, vf[j].y);                        \
                    }                                                           \
                }                                                               \
            }                                                                   \
        }

    // prologue: chunk 0 -> buf 0
    P1_LOAD(0, 4, 0, 0)

    // c = 0
    asm volatile("cp.async.wait_group 0;");
    __syncthreads();
    P1_LOAD(1, 4, 4, 1)
    P1_COMPUTE(4, 0)
    // c = 1
    asm volatile("cp.async.wait_group 0;");
    __syncthreads();
    P1_LOAD(2, 3, 8, 0)
    P1_COMPUTE(4, 1)
    // c = 2
    asm volatile("cp.async.wait_group 0;");
    __syncthreads();
    P1_LOAD(3, 3, 11, 1)
    P1_COMPUTE(3, 0)
    // c = 3
    asm volatile("cp.async.wait_group 0;");
    __syncthreads();
    P1_COMPUTE(3, 1)

    float res[8][4];
    #pragma unroll
    for (int i = 0; i < 8; i++)
        #pragma unroll
        for (int j = 0; j < 4; j++) {
            float2 f = unpack2(acc[i][j]);
            res[i][j] = f.x + f.y;
        }

    __syncthreads();
    float* sRed = (float*)smem;         // 24 KB < 59 KB
    if (warp) {
        #pragma unroll
        for (int i = 0; i < 8; i++)
            #pragma unroll
            for (int j = 0; j < 4; j++)
                sRed[(warp - 1) * 1024 + (d1g + 4 * i) * 32 + d2g + 8 * j] = res[i][j];
    }
    __syncthreads();
    if (!warp) {
        float* o = &g_part[((batch << 2) | rm) << 10];
        #pragma unroll
        for (int i = 0; i < 8; i++)
            #pragma unroll
            for (int j = 0; j < 4; j++) {
                const int idx = (d1g + 4 * i) * 32 + d2g + 8 * j;
                float s = res[i][j];
                #pragma unroll
                for (int w = 0; w < 6; w++) s += sRed[w * 1024 + idx];
                o[idx] = s;
            }
    }
}

// ===== Pass 2 (round-10 form, measured ~18us): 1 item/CTA, whole-item q burst =====
__global__ __launch_bounds__(224, 4) void p2(const float* __restrict__ Q,
                                             float* __restrict__ O) {
    extern __shared__ float4 dsm[];
    float4* sQ = dsm;                          // [1792] f4: 32 ch x 56 quads
    float*  sM = (float*)(dsm + 1792);         // [1024] f32

    const int tid  = threadIdx.x;
    const int item = blockIdx.x;               // 0..895
    const int b    = item / 7;
    const int rb   = item - b * 7;
    const int h    = b & 7;
    const int win  = (b >> 3) & 1;
    const int tb   = b >> 4;
    const int ibase = (tb * 256 + h * 32) * HW4 + win * 7 + rb * 112;

    const float4* Q4 = (const float4*)Q;
    float4* O4 = (float4*)O;

    #pragma unroll
    for (int t = 0; t < 8; ++t) {
        int i  = tid + t * 224;
        int ch = i / 56;
        int qd = i - ch * 56;
        cp16(&sQ[i], Q4 + ibase + ch * HW4 + (qd / 7) * 14 + (qd - (qd / 7) * 7));
    }
    asm volatile("cp.async.commit_group;");

    // M staging: 4 rowmod partials reduced + scale folded
    {
        const float4* gp4 = (const float4*)&g_part[b << 12];
        float4* sM4 = (float4*)sM;
        for (int i = tid; i < 256; i += 224) {
            float4 a = gp4[i], bb = gp4[256 + i];
            float4 c = gp4[512 + i], dd = gp4[768 + i];
            sM4[i] = make_float4(((a.x + bb.x) + (c.x + dd.x)) * SCALE2,
                                 ((a.y + bb.y) + (c.y + dd.y)) * SCALE2,
                                 ((a.z + bb.z) + (c.z + dd.z)) * SCALE2,
                                 ((a.w + bb.w) + (c.w + dd.w)) * SCALE2);
        }
    }

    asm volatile("cp.async.wait_group 0;");
    __syncthreads();

    const int cg   = tid & 3;
    const int quad = tid >> 2;                 // 0..55
    const int base4 = ibase + (quad / 7) * 14 + (quad - (quad / 7) * 7);

    const float4* q  = &sQ[quad];
    const float*  Ms = &sM[cg * 8];

    unsigned long long acc[4][4];
    #pragma unroll
    for (int p = 0; p < 4; p++)
        #pragma unroll
        for (int j = 0; j < 4; j++) acc[p][j] = 0ull;

    #pragma unroll
    for (int d = 0; d < 32; ++d) {
        float4 qv = q[d * 56];
        const ulonglong2* mr = reinterpret_cast<const ulonglong2*>(Ms + d * 32);
        ulonglong2 m0 = mr[0], m1 = mr[1];
        unsigned long long q0 = pack2(qv.x, qv.x);
        unsigned long long q1 = pack2(qv.y, qv.y);
        unsigned long long q2 = pack2(qv.z, qv.z);
        unsigned long long q3 = pack2(qv.w, qv.w);
        FFMA2(acc[0][0], q0, m0.x); FFMA2(acc[0][1], q0, m0.y);
        FFMA2(acc[0][2], q0, m1.x); FFMA2(acc[0][3], q0, m1.y);
        FFMA2(acc[1][0], q1, m0.x); FFMA2(acc[1][1], q1, m0.y);
        FFMA2(acc[1][2], q1, m1.x); FFMA2(acc[1][3], q1, m1.y);
        FFMA2(acc[2][0], q2, m0.x); FFMA2(acc[2][1], q2, m0.y);
        FFMA2(acc[2][2], q2, m1.x); FFMA2(acc[2][3], q2, m1.y);
        FFMA2(acc[3][0], q3, m0.x); FFMA2(acc[3][1], q3, m0.y);
        FFMA2(acc[3][2], q3, m1.x); FFMA2(acc[3][3], q3, m1.y);
    }

    #pragma unroll
    for (int j = 0; j < 4; ++j) {
        float2 a0 = unpack2(acc[0][j]);
        float2 a1 = unpack2(acc[1][j]);
        float2 a2 = unpack2(acc[2][j]);
        float2 a3 = unpack2(acc[3][j]);
        float4 lo = make_float4(a0.x, a1.x, a2.x, a3.x);
        float4 hi = make_float4(a0.y, a1.y, a2.y, a3.y);
        O4[base4 + (cg * 8 + 2 * j)     * HW4] = lo;
        O4[base4 + (cg * 8 + 2 * j + 1) * HW4] = hi;
    }
}

extern "C" void kernel_launch(void* const* d_in, const int* in_sizes, int n_in,
                              void* d_out, int out_size) {
    const float* q = (const float*)d_in[0];
    const float* k = (const float*)d_in[1];
    const float* v = (const float*)d_in[2];
    float* o = (float*)d_out;

    cudaFuncSetAttribute(p1, cudaFuncAttributeMaxDynamicSharedMemorySize, P1_SMEM);
    cudaFuncSetAttribute(p2, cudaFuncAttributeMaxDynamicSharedMemorySize, P2_SMEM);
    p1<<<dim3(4, NB), 224, P1_SMEM>>>(k, v);
    p2<<<896, 224, P2_SMEM>>>(q, o);
}

// round 16
// speedup vs baseline: 1.0069x; 1.0069x over previous
#include <cuda_runtime.h>

// LePEAttention: out = Q (K^T V) * 2/sqrt(32); no softmax. 128 batches (t,b,win,head),
// each: Q,K,V = [32 ch][1568 pos], pos = 56 rows x 28 cols (win selects col half).

#define HW4    784                 // 3136/4
#define NB     128
#define SROW   29                  // k/v row stride in float4 units (28 + 1 pad)
#define CH_F4  (32 * SROW)
#define BUF_F4 (2 * CH_F4)         // K + V one chunk (<=4 strided rows)
#define P1_SMEM (2 * BUF_F4 * 16)  // 59392 B double buffered -> 3 CTAs/SM
#define P2_SMEM 32768              // sQ[1792] f4 + sM[1024] f32
#define SCALE2 0.35355339059327373f

__device__ float g_part[NB * 4 * 1024];   // 4 rowmod-partials per batch

#define FFMA2(d, a, b) \
    asm("fma.rn.f32x2 %0, %1, %2, %0;" : "+l"(d) : "l"(a), "l"(b))

__device__ __forceinline__ unsigned long long pack2(float x, float y) {
    unsigned long long r;
    asm("mov.b64 %0, {%1,%2};" : "=l"(r) : "f"(x), "f"(y));
    return r;
}
__device__ __forceinline__ float2 unpack2(unsigned long long a) {
    float2 f;
    asm("mov.b64 {%0,%1}, %2;" : "=f"(f.x), "=f"(f.y) : "l"(a));
    return f;
}
__device__ __forceinline__ void cp16(void* dst, const void* src) {
    unsigned d = (unsigned)__cvta_generic_to_shared(dst);
    asm volatile("cp.async.cg.shared.global [%0], [%1], 16;" :: "r"(d), "l"(src));
}

// ===== Pass 1: M partial over rows {rm, rm+4, ..., rm+52}; 512 CTAs, 3/SM =====
// chunk c covers strided-row indices k in [KB[c], KB[c]+NK[c]):
//   KB = {0,4,8,11}, NK = {4,4,3,3}  (14 strided rows total)
__global__ __launch_bounds__(224, 3) void p1(const float* __restrict__ K,
                                             const float* __restrict__ V) {
    extern __shared__ float4 smem[];

    const int tid   = threadIdx.x;
    const int rm    = blockIdx.x;       // row mod 4
    const int batch = blockIdx.y;
    const int h   = batch & 7;
    const int win = (batch >> 3) & 1;
    const int tb  = batch >> 4;
    const int base4 = (tb * 256 + h * 32) * HW4 + win * 7;

    const float4* Kp = (const float4*)K;
    const float4* Vp = (const float4*)V;

    // affine slot geometry: slot t covers ch = ch0 + 8t (224 = 8*28)
    const int ch0     = tid / 28;
    const int u0      = tid - ch0 * 28;       // 0..27 = k_local*7 + cu
    const int k_local = u0 / 7;               // 0..3
    const int smK     = ch0 * SROW + u0;      // f4 units
    const int gK      = base4 + ch0 * HW4 + (rm + 4 * k_local) * 14 + (u0 - k_local * 7);

    const int lane = tid & 31;
    const int warp = tid >> 5;          // 7 warps
    const int d1g  = lane & 3;          // k-ch {d1g + 4i}
    const int d2g  = lane >> 2;         // v-ch {d2g + 8j}: stride 29 odd -> CF

    unsigned long long acc[8][4];
    #pragma unroll
    for (int i = 0; i < 8; i++)
        #pragma unroll
        for (int j = 0; j < 4; j++) acc[i][j] = 0ull;

    // load chunk c into buffer buf (predicated on k_local < NK[c])
    #define P1_LOAD(c_, nk_, kb_, buf_)                                         \
        if (k_local < (nk_)) {                                                  \
            _Pragma("unroll")                                                   \
            for (int t = 0; t < 4; ++t) {                                       \
                cp16(&smem[(buf_) * BUF_F4 + smK + t * 8 * SROW],               \
                     Kp + gK + (kb_) * 56 + t * 8 * HW4);                       \
                cp16(&smem[(buf_) * BUF_F4 + CH_F4 + smK + t * 8 * SROW],       \
                     Vp + gK + (kb_) * 56 + t * 8 * HW4);                       \
            }                                                                   \
        }                                                                       \
        asm volatile("cp.async.commit_group;");

    #define P1_COMPUTE(nk_, buf_)                                               \
        {                                                                       \
            const float4* sK = &smem[(buf_) * BUF_F4];                          \
            const float4* sV = sK + CH_F4;                                      \
            _Pragma("unroll")                                                   \
            for (int qq = 0; qq < (nk_); ++qq) {                                \
                const int p4 = (nk_) * warp + qq;                               \
                ulonglong2 vf[4];                                               \
                _Pragma("unroll")                                               \
                for (int j = 0; j < 4; j++)                                     \
                    vf[j] = *reinterpret_cast<const ulonglong2*>(               \
                        &sV[(d2g + 8 * j) * SROW + p4]);                        \
                _Pragma("unroll")                                               \
                for (int i = 0; i < 8; i++) {                                   \
                    ulonglong2 kf = *reinterpret_cast<const ulonglong2*>(       \
                        &sK[(d1g + 4 * i) * SROW + p4]);                        \
                    _Pragma("unroll")                                           \
                    for (int j = 0; j < 4; j++) {                               \
                        FFMA2(acc[i][j], kf.x, vf[j].x);                        \
                        FFMA2(acc[i][j], kf.y, vf[j].y);                        \
                    }                                                           \
                }                                                               \
            }                                                                   \
        }

    // prologue: chunk 0 -> buf 0
    P1_LOAD(0, 4, 0, 0)

    // c = 0
    asm volatile("cp.async.wait_group 0;");
    __syncthreads();
    P1_LOAD(1, 4, 4, 1)
    P1_COMPUTE(4, 0)
    // c = 1
    asm volatile("cp.async.wait_group 0;");
    __syncthreads();
    P1_LOAD(2, 3, 8, 0)
    P1_COMPUTE(4, 1)
    // c = 2
    asm volatile("cp.async.wait_group 0;");
    __syncthreads();
    P1_LOAD(3, 3, 11, 1)
    P1_COMPUTE(3, 0)
    // c = 3
    asm volatile("cp.async.wait_group 0;");
    __syncthreads();
    P1_COMPUTE(3, 1)

    float res[8][4];
    #pragma unroll
    for (int i = 0; i < 8; i++)
        #pragma unroll
        for (int j = 0; j < 4; j++) {
            float2 f = unpack2(acc[i][j]);
            res[i][j] = f.x + f.y;
        }

    __syncthreads();
    float* sRed = (float*)smem;         // 24 KB < 59 KB
    if (warp) {
        #pragma unroll
        for (int i = 0; i < 8; i++)
            #pragma unroll
            for (int j = 0; j < 4; j++)
                sRed[(warp - 1) * 1024 + (d1g + 4 * i) * 32 + d2g + 8 * j] = res[i][j];
    }
    __syncthreads();
    if (!warp) {
        float* o = &g_part[((batch << 2) | rm) << 10];
        #pragma unroll
        for (int i = 0; i < 8; i++)
            #pragma unroll
            for (int j = 0; j < 4; j++) {
                const int idx = (d1g + 4 * i) * 32 + d2g + 8 * j;
                float s = res[i][j];
                #pragma unroll
                for (int w = 0; w < 6; w++) s += sRed[w * 1024 + idx];
                o[idx] = s;
            }
    }
}

// ===== Pass 2 (round-10 form, measured ~18us): 1 item/CTA, whole-item q burst =====
__global__ __launch_bounds__(224, 4) void p2(const float* __restrict__ Q,
                                             float* __restrict__ O) {
    extern __shared__ float4 dsm[];
    float4* sQ = dsm;                          // [1792] f4: 32 ch x 56 quads
    float*  sM = (float*)(dsm + 1792);         // [1024] f32

    const int tid  = threadIdx.x;
    const int item = blockIdx.x;               // 0..895
    const int b    = item / 7;
    const int rb   = item - b * 7;
    const int h    = b & 7;
    const int win  = (b >> 3) & 1;
    const int tb   = b >> 4;
    const int ibase = (tb * 256 + h * 32) * HW4 + win * 7 + rb * 112;

    const float4* Q4 = (const float4*)Q;
    float4* O4 = (float4*)O;

    #pragma unroll
    for (int t = 0; t < 8; ++t) {
        int i  = tid + t * 224;
        int ch = i / 56;
        int qd = i - ch * 56;
        cp16(&sQ[i], Q4 + ibase + ch * HW4 + (qd / 7) * 14 + (qd - (qd / 7) * 7));
    }
    asm volatile("cp.async.commit_group;");

    // M staging: 4 rowmod partials reduced + scale folded
    {
        const float4* gp4 = (const float4*)&g_part[b << 12];
        float4* sM4 = (float4*)sM;
        for (int i = tid; i < 256; i += 224) {
            float4 a = gp4[i], bb = gp4[256 + i];
            float4 c = gp4[512 + i], dd = gp4[768 + i];
            sM4[i] = make_float4(((a.x + bb.x) + (c.x + dd.x)) * SCALE2,
                                 ((a.y + bb.y) + (c.y + dd.y)) * SCALE2,
                                 ((a.z + bb.z) + (c.z + dd.z)) * SCALE2,
                                 ((a.w + bb.w) + (c.w + dd.w)) * SCALE2);
        }
    }

    asm volatile("cp.async.wait_group 0;");
    __syncthreads();

    const int cg   = tid & 3;
    const int quad = tid >> 2;                 // 0..55
    const int base4 = ibase + (quad / 7) * 14 + (quad - (quad / 7) * 7);

    const float4* q  = &sQ[quad];
    const float*  Ms = &sM[cg * 8];

    unsigned long long acc[4][4];
    #pragma unroll
    for (int p = 0; p < 4; p++)
        #pragma unroll
        for (int j = 0; j < 4; j++) acc[p][j] = 0ull;

    #pragma unroll
    for (int d = 0; d < 32; ++d) {
        float4 qv = q[d * 56];
        const ulonglong2* mr = reinterpret_cast<const ulonglong2*>(Ms + d * 32);
        ulonglong2 m0 = mr[0], m1 = mr[1];
        unsigned long long q0 = pack2(qv.x, qv.x);
        unsigned long long q1 = pack2(qv.y, qv.y);
        unsigned long long q2 = pack2(qv.z, qv.z);
        unsigned long long q3 = pack2(qv.w, qv.w);
        FFMA2(acc[0][0], q0, m0.x); FFMA2(acc[0][1], q0, m0.y);
        FFMA2(acc[0][2], q0, m1.x); FFMA2(acc[0][3], q0, m1.y);
        FFMA2(acc[1][0], q1, m0.x); FFMA2(acc[1][1], q1, m0.y);
        FFMA2(acc[1][2], q1, m1.x); FFMA2(acc[1][3], q1, m1.y);
        FFMA2(acc[2][0], q2, m0.x); FFMA2(acc[2][1], q2, m0.y);
        FFMA2(acc[2][2], q2, m1.x); FFMA2(acc[2][3], q2, m1.y);
        FFMA2(acc[3][0], q3, m0.x); FFMA2(acc[3][1], q3, m0.y);
        FFMA2(acc[3][2], q3, m1.x); FFMA2(acc[3][3], q3, m1.y);
    }

    #pragma unroll
    for (int j = 0; j < 4; ++j) {
        float2 a0 = unpack2(acc[0][j]);
        float2 a1 = unpack2(acc[1][j]);
        float2 a2 = unpack2(acc[2][j]);
        float2 a3 = unpack2(acc[3][j]);
        float4 lo = make_float4(a0.x, a1.x, a2.x, a3.x);
        float4 hi = make_float4(a0.y, a1.y, a2.y, a3.y);
        O4[base4 + (cg * 8 + 2 * j)     * HW4] = lo;
        O4[base4 + (cg * 8 + 2 * j + 1) * HW4] = hi;
    }
}

extern "C" void kernel_launch(void* const* d_in, const int* in_sizes, int n_in,
                              void* d_out, int out_size) {
    const float* q = (const float*)d_in[0];
    const float* k = (const float*)d_in[1];
    const float* v = (const float*)d_in[2];
    float* o = (float*)d_out;

    cudaFuncSetAttribute(p1, cudaFuncAttributeMaxDynamicSharedMemorySize, P1_SMEM);
    cudaFuncSetAttribute(p2, cudaFuncAttributeMaxDynamicSharedMemorySize, P2_SMEM);
    p1<<<dim3(4, NB), 224, P1_SMEM>>>(k, v);
    p2<<<896, 224, P2_SMEM>>>(q, o);
}